// round 11
// baseline (speedup 1.0000x reference)
#include <cuda_runtime.h>
#include <math_constants.h>

#define NFLOWS 8
#define SUBSTR 68            // padded row stride (floats) -> 16B-aligned rows

// ---------------------------------------------------------------------------
// Device-global precomputed tables (no allocations anywhere — harness rule)
// ---------------------------------------------------------------------------
__device__ __align__(16) float  g_hdr[NFLOWS][80];          // [0:64] sorted thr, [64:73] wc, [73:76] c
__device__ __align__(16) float  g_sub[NFLOWS][65 * SUBSTR]; // [s*68+j] sorted sub-breakpoints (+INF pads)
__device__ float4 g_coef[NFLOWS][4225][2];                  // [s*65+j]: {alpha0..3},{beta0..3}
__device__ float  g_L[9], g_bm[3], g_totc;

// ---------------------------------------------------------------------------
// Fused prep (byte-identical to R10): grid (65, 8) x 256 threads.
// ALL FP32 (B300 vector fp64 ~2 lane-ops/cyc/SM — R6 regression).
// ---------------------------------------------------------------------------
__global__ __launch_bounds__(256)
void k_prep(const float* __restrict__ L_tril, const float* __restrict__ bm,
            const float* __restrict__ ls, const float* __restrict__ sh,
            const float* __restrict__ P,  const float* __restrict__ ss,
            const float* __restrict__ lm, const float* __restrict__ um,
            const float* __restrict__ lls,
            const float* __restrict__ W1, const float* __restrict__ b1,
            const float* __restrict__ W2, const float* __restrict__ b2,
            const float* __restrict__ W3, const float* __restrict__ b3) {
    __shared__ float  sW2[4096];
    __shared__ float  sa[64], sbv[64], sthr[64], sx[64];
    __shared__ int    srank[64], ssub[64];
    __shared__ float  sP[64], sQ[64];
    __shared__ unsigned char sin_[64], sact0[64];
    __shared__ float  sw3[4][64];
    __shared__ float  sb3v[4];

    const int s = blockIdx.x;   // 0..64
    const int f = blockIdx.y;
    const int t = threadIdx.x;

    for (int i = t; i < 4096; i += 256) sW2[i] = W2[f * 4096 + i];
    if (t < 64) {
        float a = W1[f * 64 + t], b = b1[f * 64 + t];
        sa[t] = a; sbv[t] = b;
        sx[t] = (a != 0.f) ? (-b / a) : CUDART_INF_F;   // raw thresholds (temp in sx)
        sw3[0][t] = W3[f * 256 + t];
        sw3[1][t] = W3[f * 256 + 64 + t];
        sw3[2][t] = W3[f * 256 + 128 + t];
        sw3[3][t] = W3[f * 256 + 192 + t];
    }
    if (t >= 64 && t < 68) sb3v[t - 64] = b3[f * 4 + (t - 64)];
    __syncthreads();

    // per-block redundant rank sort of the 64 layer-1 breakpoints
    if (t < 64) {
        float tk = sx[t];
        int r = 0;
        for (int j = 0; j < 64; ++j) {
            float tj = sx[j];
            r += (tj < tk) || (tj == tk && j < t);
        }
        srank[t] = r;
        sthr[r] = tk;
    }
    __syncthreads();

    // block s==0 of each flow publishes the header
    if (s == 0) {
        if (t < 64) g_hdr[f][t] = sthr[t];
        if (t == 64) {
            float el[3], shv[3];
            for (int d = 0; d < 3; d++) { el[d] = expf(ls[f * 3 + d]); shv[d] = sh[f * 3 + d]; }
            float l[3][3], U[3][3];
            for (int aa = 0; aa < 3; aa++)
                for (int bb = 0; bb < 3; bb++) {
                    l[aa][bb] = (bb < aa ? lm[f * 9 + aa * 3 + bb] : (aa == bb ? 1.f : 0.f));
                    U[aa][bb] = (bb > aa ? um[f * 9 + aa * 3 + bb] : 0.f);
                }
            for (int d = 0; d < 3; d++) U[d][d] = ss[f * 3 + d] * expf(lls[f * 3 + d]);
            float A[3][3], Wm[3][3];
            for (int aa = 0; aa < 3; aa++)
                for (int bb = 0; bb < 3; bb++) {
                    float s2 = 0.f;
                    for (int q = 0; q < 3; q++) s2 += l[aa][q] * U[q][bb];
                    A[aa][bb] = s2;
                }
            for (int aa = 0; aa < 3; aa++)
                for (int bb = 0; bb < 3; bb++) {
                    float s2 = 0.f;
                    for (int q = 0; q < 3; q++) s2 += P[f * 9 + aa * 3 + q] * A[q][bb];
                    Wm[aa][bb] = s2;
                }
            for (int aa = 0; aa < 3; aa++) {
                float cs = 0.f;
                for (int bb = 0; bb < 3; bb++) {
                    float wcv = Wm[aa][bb] * el[bb];
                    g_hdr[f][64 + aa * 3 + bb] = wcv;
                    cs += wcv * shv[bb];
                }
                g_hdr[f][73 + aa] = cs;
            }
        }
        if (f == 0 && t == 65) {
            float Lt[3][3], cov[3][3];
            for (int aa = 0; aa < 3; aa++)
                for (int bb = 0; bb < 3; bb++)
                    Lt[aa][bb] = (bb <= aa ? L_tril[aa * 3 + bb] : 0.f) + (aa == bb ? 1e-6f : 0.f);
            for (int aa = 0; aa < 3; aa++)
                for (int bb = 0; bb < 3; bb++) {
                    float s2 = 0.f;
                    for (int q = 0; q < 3; q++) s2 += Lt[aa][q] * Lt[bb][q];
                    cov[aa][bb] = s2;
                }
            float L00 = sqrtf(cov[0][0]);
            float L10 = cov[1][0] / L00, L20 = cov[2][0] / L00;
            float L11 = sqrtf(cov[1][1] - L10 * L10);
            float L21 = (cov[2][1] - L20 * L10) / L11;
            float L22 = sqrtf(cov[2][2] - L20 * L20 - L21 * L21);
            float Lm[9] = {L00, 0.f, 0.f, L10, L11, 0.f, L20, L21, L22};
            for (int q = 0; q < 9; q++) g_L[q] = Lm[q];
            for (int q = 0; q < 3; q++) g_bm[q] = bm[q];
        }
        if (f == 0 && t == 66) {
            float tot = 0.f;
            for (int q = 0; q < NFLOWS * 3; q++) tot += ls[q] + lls[q];
            g_totc = tot;
        }
    }

    const float lo = (s == 0)  ? -CUDART_INF_F : sthr[s - 1];
    const float hi = (s == 64) ?  CUDART_INF_F : sthr[s];

    if (t < 64) {
        const int u = t;
        float Pd = 0.f, Qd = b2[f * 64 + u];
        for (int j = 0; j < 64; ++j) {
            float aj = sa[j];
            bool act = (aj > 0.f) ? (srank[j] < s)
                     : (aj < 0.f) ? (srank[j] >= s)
                                  : (sbv[j] > 0.f);
            if (act) {
                float w = sW2[u * 64 + j];
                Pd = fmaf(w, aj, Pd);
                Qd = fmaf(w, sbv[j], Qd);
            }
        }
        sP[u] = Pd; sQ[u] = Qd;
        float xu = (Pd != 0.f) ? (-Qd / Pd) : CUDART_INF_F;
        bool inside = (Pd != 0.f) && (xu > lo) && (xu < hi);
        sx[u]  = inside ? xu : CUDART_INF_F;
        sin_[u] = inside ? 1 : 0;
        bool a0;                                // active just above lo?
        if (Pd > 0.f)      a0 = (xu <= lo);
        else if (Pd < 0.f) a0 = (xu > lo);
        else               a0 = (Qd > 0.f);
        sact0[u] = a0 ? 1 : 0;
    }
    __syncthreads();
    if (t < 64) {
        float key = sx[t];
        int r = 0;
        for (int j = 0; j < 64; ++j) {
            float xj = sx[j];
            r += (xj < key) || (xj == key && j < t);
        }
        ssub[t] = r;
        g_sub[f][s * SUBSTR + r] = key;           // sorted (INF entries at top)
    }
    if (t >= 64 && t < 68)                        // pads 64..67 = +INF
        g_sub[f][s * SUBSTR + t] = CUDART_INF_F;
    __syncthreads();

    // coef build: thread t -> (j = t>>2, r = t&3); j=64 handled by t<4 after
    {
        int j = t >> 2, r = t & 3;
        for (int pass = 0; pass < 2; ++pass) {
            if (pass == 1) { if (t >= 4) break; j = 64; r = t; }
            float al = 0.f, be = sb3v[r];
            const float* w3r = sw3[r];
            for (int u = 0; u < 64; ++u) {
                bool act = (sact0[u] != 0) != ((sin_[u] != 0) && (ssub[u] < j));
                if (act) {
                    float w = w3r[u];
                    al = fmaf(w, sP[u], al);
                    be = fmaf(w, sQ[u], be);
                }
            }
            float* dst = (float*)&g_coef[f][s * 65 + j][0];
            dst[r] = al; dst[4 + r] = be;
        }
    }
}

// ---------------------------------------------------------------------------
// Main kernel: 512 thr/CTA, ONE sample per thread -> 262144 threads chip-wide,
// ~55 warps/SM (was 13.6 at 4 samples/thread — the R10 latency limiter).
// No smem, no barriers; all tables via __ldg (L1-resident per flow).
// Coarse: 8 uniform pivot loads -> ALU octant -> one aligned 32B gather.
// Fine: float4 linear scan (INF-padded, avg ~1 load).
// ---------------------------------------------------------------------------
__global__ __launch_bounds__(512)
void glow_main(const float* __restrict__ eps, float* __restrict__ out, int N) {
    int gi = blockIdx.x * 512 + threadIdx.x;
    const bool valid = gi < N;
    const int i = valid ? gi : (N - 1);

    const float L0 = g_L[0], L3 = g_L[3], L4 = g_L[4],
                L6 = g_L[6], L7 = g_L[7], L8 = g_L[8];
    const float m0 = g_bm[0], m1 = g_bm[1], m2 = g_bm[2];

    float e0 = eps[3 * i], e1 = eps[3 * i + 1], e2 = eps[3 * i + 2];
    float z0 = m0 + L0 * e0;
    float z1 = m1 + L3 * e0 + L4 * e1;
    float z2 = m2 + L6 * e0 + L7 * e1 + L8 * e2;
    float ld = 0.f;

    #pragma unroll
    for (int f = 0; f < NFLOWS; ++f) {
        const float* hdr = g_hdr[f];

        // conv constants (uniform-address broadcast loads)
        float4 h0 = __ldg((const float4*)(hdr + 64));
        float4 h1 = __ldg((const float4*)(hdr + 68));
        float4 h2 = __ldg((const float4*)(hdr + 72));

        float n0 = h2.y + h0.x * z0 + h0.y * z1 + h0.z * z2;
        float n1 = h2.z + h0.w * z0 + h1.x * z1 + h1.y * z2;
        float n2 = h2.w + h1.z * z0 + h1.w * z1 + h2.x * z2;
        z0 = n0; z1 = n1; z2 = n2;

        // pivots thr[7], thr[15], ..., thr[63] (uniform broadcast)
        float pv0 = __ldg(hdr + 7),  pv1 = __ldg(hdr + 15);
        float pv2 = __ldg(hdr + 23), pv3 = __ldg(hdr + 31);
        float pv4 = __ldg(hdr + 39), pv5 = __ldg(hdr + 47);
        float pv6 = __ldg(hdr + 55), pv7 = __ldg(hdr + 63);

        // coarse rank s in [0,64]: octant by ALU, then one aligned 8-float gather
        int o = (pv0 < z0) + (pv1 < z0) + (pv2 < z0) + (pv3 < z0)
              + (pv4 < z0) + (pv5 < z0) + (pv6 < z0) + (pv7 < z0);
        int ob = (o > 7 ? 7 : o) * 8;
        float4 t0 = __ldg((const float4*)(hdr + ob));
        float4 t1 = __ldg((const float4*)(hdr + ob + 4));
        int sS = ob
               + (t0.x < z0) + (t0.y < z0) + (t0.z < z0) + (t0.w < z0)
               + (t1.x < z0) + (t1.y < z0) + (t1.z < z0) + (t1.w < z0);

        // fine rank j in [0,64]: float4 linear scan (INF-padded, avg 1 load)
        const float4* row = (const float4*)(g_sub[f] + sS * SUBSTR);
        float4 v = __ldg(row);
        int c = (v.x < z0) + (v.y < z0) + (v.z < z0) + (v.w < z0);
        int jS = c;
        while (c == 4) {
            float4 w = __ldg(row + (jS >> 2));
            c = (w.x < z0) + (w.y < z0) + (w.z < z0) + (w.w < z0);
            jS += c;
        }

        // exact affine MLP output + coupling
        const float4* cp = &g_coef[f][sS * 65 + jS][0];
        float4 al = __ldg(cp), be = __ldg(cp + 1);
        float o0 = fmaf(al.x, z0, be.x), o1 = fmaf(al.y, z0, be.y);
        float o2 = fmaf(al.z, z0, be.z), o3 = fmaf(al.w, z0, be.w);
        z1 = fmaf(z1, __expf(o2), o0);
        z2 = fmaf(z2, __expf(o3), o1);
        ld += o2 + o3;
    }

    if (valid) {
        out[3 * i]     = z0;
        out[3 * i + 1] = __expf(z1);
        out[3 * i + 2] = __expf(z2);
        out[3 * N + i] = ld + g_totc + z1 + z2;
    }
}

// ---------------------------------------------------------------------------
// Launch. Inputs (metadata order): eps, L_tril, base_mean, an_log_scale,
// an_shift, perm_p, sign_s, lu_l, lu_u, lu_log_s, W1, b1, W2, b2, W3, b3
// Output: [z_t (N,3) row-major][log_det (N)] float32 (layout verified R4..R10)
// ---------------------------------------------------------------------------
extern "C" void kernel_launch(void* const* d_in, const int* in_sizes, int n_in,
                              void* d_out, int out_size) {
    const float* eps    = (const float*)d_in[0];
    const float* L_tril = (const float*)d_in[1];
    const float* bm     = (const float*)d_in[2];
    const float* an_ls  = (const float*)d_in[3];
    const float* an_sh  = (const float*)d_in[4];
    const float* perm   = (const float*)d_in[5];
    const float* ss     = (const float*)d_in[6];
    const float* lu_l   = (const float*)d_in[7];
    const float* lu_u   = (const float*)d_in[8];
    const float* lu_ls  = (const float*)d_in[9];
    const float* W1     = (const float*)d_in[10];
    const float* b1     = (const float*)d_in[11];
    const float* W2     = (const float*)d_in[12];
    const float* b2     = (const float*)d_in[13];
    const float* W3     = (const float*)d_in[14];
    const float* b3     = (const float*)d_in[15];
    float* out = (float*)d_out;

    int N = in_sizes[0] / 3;

    k_prep<<<dim3(65, NFLOWS), 256>>>(L_tril, bm, an_ls, an_sh, perm, ss,
                                      lu_l, lu_u, lu_ls, W1, b1, W2, b2, W3, b3);
    glow_main<<<(N + 511) / 512, 512>>>(eps, out, N);
}